// round 2
// baseline (speedup 1.0000x reference)
#include <cuda_runtime.h>
#include <cuda_bf16.h>
#include <math.h>

// ---------------- problem constants (fixed dataset shapes) ----------------
#define NTOK 8192      // B*S = 4*2048
#define H    1024
#define F    4096
#define E    8
#define TOPK 2
#define CAP  1280      // ceil(NTOK/E * 1.25)
#define NASG (NTOK*TOPK)   // 16384
#define MAXL NTOK          // max assignments per expert (top-2 distinct experts)

// ---------------- device scratch (bss, zero-initialized at load) ----------
__device__ float              g_comb[(size_t)NTOK * H];        // 33.5 MB combine buffer
__device__ float              g_h1[(size_t)E * CAP * F];       // 167.8 MB intermediate
__device__ unsigned long long g_key[E * MAXL];                 // sortable keys per expert
__device__ int                g_aid[E * MAXL];                 // assignment id per bucket slot
__device__ int                g_cnt[E];                        // bucket counts
__device__ int                g_kept[E];                       // min(cnt, CAP)
__device__ int                g_tok[E * CAP];                  // kept token per slot
__device__ float              g_gate[E * CAP];                 // kept gate per slot

// ---------------- kernel 0: zero combine buffer + counters ----------------
__global__ void zero_kernel() {
    size_t idx = (size_t)blockIdx.x * blockDim.x + threadIdx.x;
    size_t total = (size_t)NTOK * H;
    for (size_t i = idx; i < total; i += (size_t)gridDim.x * blockDim.x)
        g_comb[i] = 0.0f;
    if (idx < E) g_cnt[idx] = 0;
}

// ---------------- kernel 1: router (logits, top-2, softmax, bucket push) --
__global__ void router_kernel(const float* __restrict__ x,
                              const float* __restrict__ Wr,
                              const float* __restrict__ br) {
    int warp = (blockIdx.x * blockDim.x + threadIdx.x) >> 5;
    int lane = threadIdx.x & 31;
    if (warp >= NTOK) return;
    const float* xr = x + (size_t)warp * H;

    float acc[E];
#pragma unroll
    for (int e = 0; e < E; e++) acc[e] = 0.0f;

    for (int k = lane; k < H; k += 32) {
        float xv = xr[k];
        const float* w = Wr + (size_t)k * E;
#pragma unroll
        for (int e = 0; e < E; e++) acc[e] += xv * w[e];
    }
    // warp reduce all 8 logits
#pragma unroll
    for (int e = 0; e < E; e++) {
#pragma unroll
        for (int off = 16; off > 0; off >>= 1)
            acc[e] += __shfl_xor_sync(0xffffffffu, acc[e], off);
    }

    if (lane == 0) {
        float lg[E];
#pragma unroll
        for (int e = 0; e < E; e++) lg[e] = acc[e] + br[e];
        // top-1 (lowest index on tie via strict >)
        float b1v = -1e38f; int b1i = 0;
#pragma unroll
        for (int e = 0; e < E; e++)
            if (lg[e] > b1v) { b1v = lg[e]; b1i = e; }
        // top-2
        float b2v = -1e38f; int b2i = 0;
#pragma unroll
        for (int e = 0; e < E; e++)
            if (e != b1i && lg[e] > b2v) { b2v = lg[e]; b2i = e; }
        // softmax over the two (matches jax: exp(v-max)/sum)
        float ed = expf(b2v - b1v);
        float inv = 1.0f / (1.0f + ed);
        float w1 = inv;
        float w2 = ed * inv;

        int a0 = warp * TOPK;       // first assignment (larger weight)
        int a1 = a0 + 1;
        unsigned long long k0 =
            ((unsigned long long)__float_as_uint(w1) << 32) | (0xFFFFFFFFu - (unsigned)a0);
        unsigned long long k1 =
            ((unsigned long long)__float_as_uint(w2) << 32) | (0xFFFFFFFFu - (unsigned)a1);
        int p0 = atomicAdd(&g_cnt[b1i], 1);
        g_key[b1i * MAXL + p0] = k0;
        g_aid[b1i * MAXL + p0] = a0;
        int p1 = atomicAdd(&g_cnt[b2i], 1);
        g_key[b2i * MAXL + p1] = k1;
        g_aid[b2i * MAXL + p1] = a1;
    }
}

// ---------------- kernel 2: per-expert exact top-CAP rank & compact -------
// rank = #{j : key_j > key_i}. Keys are unique (index in low bits), so ranks
// are unique -> deterministic compact at slot=rank. Matches jax top_k order
// (descending value, ties -> lower assignment index).
__global__ void rank_kernel() {
    int e = blockIdx.x;
    int Le = g_cnt[e];
    if (blockIdx.y == 0 && threadIdx.x == 0)
        g_kept[e] = (Le < CAP) ? Le : CAP;
    const unsigned long long* keys = g_key + e * MAXL;
    for (int i = blockIdx.y * blockDim.x + threadIdx.x; i < Le;
         i += gridDim.y * blockDim.x) {
        unsigned long long ki = keys[i];
        int rank = 0;
        for (int j = 0; j < Le; j++)
            rank += (keys[j] > ki) ? 1 : 0;
        if (rank < CAP) {
            int a = g_aid[e * MAXL + i];
            g_tok[e * CAP + rank]  = a >> 1;                        // token id
            g_gate[e * CAP + rank] = __uint_as_float((unsigned)(ki >> 32));
        }
    }
}

// ---------------- GEMM 1: h1 = gelu_erf( gather(x) @ W1[e] + b1[e] ) ------
// 128x128x8 fp32 SGEMM, 256 threads, 8x8 microtile.
__global__ __launch_bounds__(256, 2)
void gemm1_kernel(const float* __restrict__ x,
                  const float* __restrict__ W1,
                  const float* __restrict__ b1) {
    const int e = blockIdx.z;
    const int kept = g_kept[e];
    const int rowBase = blockIdx.y * 128;
    if (rowBase >= kept) return;
    const int colBase = blockIdx.x * 128;

    __shared__ float As[8][128];
    __shared__ float Bs[8][128];
    __shared__ int   tokS[128];

    const int tid = threadIdx.x;
    if (tid < 128) {
        int gr = rowBase + tid;
        tokS[tid] = (gr < kept) ? g_tok[e * CAP + gr] : 0;
    }
    __syncthreads();

    const int aRow = tid >> 1;
    const int aCol = (tid & 1) * 4;
    const int bRow = tid >> 5;
    const int bCol = (tid & 31) * 4;
    const int ty = tid >> 4, tx = tid & 15;

    const float* Abase = x + (size_t)tokS[aRow] * H;
    const float* Bbase = W1 + (size_t)e * H * F + colBase;

    float acc[8][8] = {};

    for (int kt = 0; kt < H; kt += 8) {
        float4 av = *(const float4*)(Abase + kt + aCol);
        float4 bv = *(const float4*)(Bbase + (size_t)(kt + bRow) * F + bCol);
        As[aCol + 0][aRow] = av.x;
        As[aCol + 1][aRow] = av.y;
        As[aCol + 2][aRow] = av.z;
        As[aCol + 3][aRow] = av.w;
        *(float4*)&Bs[bRow][bCol] = bv;
        __syncthreads();
#pragma unroll
        for (int k = 0; k < 8; k++) {
            float a[8], b[8];
#pragma unroll
            for (int i = 0; i < 8; i++) a[i] = As[k][ty * 8 + i];
#pragma unroll
            for (int j = 0; j < 8; j++) b[j] = Bs[k][tx * 8 + j];
#pragma unroll
            for (int i = 0; i < 8; i++)
#pragma unroll
                for (int j = 0; j < 8; j++)
                    acc[i][j] = fmaf(a[i], b[j], acc[i][j]);
        }
        __syncthreads();
    }
    // epilogue: +bias, erf-GELU, store to h1 (only valid rows)
#pragma unroll
    for (int i = 0; i < 8; i++) {
        int gr = rowBase + ty * 8 + i;
        if (gr >= kept) continue;
        float* hrow = g_h1 + ((size_t)e * CAP + gr) * F + colBase;
#pragma unroll
        for (int j = 0; j < 8; j++) {
            int c = tx * 8 + j;
            float v = acc[i][j] + b1[(size_t)e * F + colBase + c];
            v = 0.5f * v * (1.0f + erff(v * 0.70710678118654752440f));
            hrow[c] = v;
        }
    }
}

// ---------------- GEMM 2: comb[tok] += gate * (h1 @ W2[e] + b2[e]) --------
__global__ __launch_bounds__(256, 2)
void gemm2_kernel(const float* __restrict__ W2,
                  const float* __restrict__ b2) {
    const int e = blockIdx.z;
    const int kept = g_kept[e];
    const int rowBase = blockIdx.y * 128;
    if (rowBase >= kept) return;
    const int colBase = blockIdx.x * 128;

    __shared__ float As[8][128];
    __shared__ float Bs[8][128];
    __shared__ int   tokS[128];
    __shared__ float gateS[128];

    const int tid = threadIdx.x;
    if (tid < 128) {
        int gr = rowBase + tid;
        if (gr < kept) {
            tokS[tid]  = g_tok[e * CAP + gr];
            gateS[tid] = g_gate[e * CAP + gr];
        } else {
            tokS[tid] = 0; gateS[tid] = 0.0f;
        }
    }
    __syncthreads();

    const int aRow = tid >> 1;
    const int aCol = (tid & 1) * 4;
    const int bRow = tid >> 5;
    const int bCol = (tid & 31) * 4;
    const int ty = tid >> 4, tx = tid & 15;

    const float* Abase = g_h1 + ((size_t)e * CAP + rowBase + aRow) * F;
    const float* Bbase = W2 + (size_t)e * F * H + colBase;

    float acc[8][8] = {};

    for (int kt = 0; kt < F; kt += 8) {
        float4 av = *(const float4*)(Abase + kt + aCol);
        float4 bv = *(const float4*)(Bbase + (size_t)(kt + bRow) * H + bCol);
        As[aCol + 0][aRow] = av.x;
        As[aCol + 1][aRow] = av.y;
        As[aCol + 2][aRow] = av.z;
        As[aCol + 3][aRow] = av.w;
        *(float4*)&Bs[bRow][bCol] = bv;
        __syncthreads();
#pragma unroll
        for (int k = 0; k < 8; k++) {
            float a[8], b[8];
#pragma unroll
            for (int i = 0; i < 8; i++) a[i] = As[k][ty * 8 + i];
#pragma unroll
            for (int j = 0; j < 8; j++) b[j] = Bs[k][tx * 8 + j];
#pragma unroll
            for (int i = 0; i < 8; i++)
#pragma unroll
                for (int j = 0; j < 8; j++)
                    acc[i][j] = fmaf(a[i], b[j], acc[i][j]);
        }
        __syncthreads();
    }
    // epilogue: +bias, gate-scale, atomic scatter into combine buffer
#pragma unroll
    for (int i = 0; i < 8; i++) {
        int r = ty * 8 + i;
        int gr = rowBase + r;
        if (gr >= kept) continue;
        int   tok = tokS[r];
        float g   = gateS[r];
        float* crow = g_comb + (size_t)tok * H + colBase;
#pragma unroll
        for (int j = 0; j < 8; j++) {
            int c = tx * 8 + j;
            float v = acc[i][j] + b2[(size_t)e * H + colBase + c];
            atomicAdd(&crow[c], g * v);
        }
    }
}

// ---------------- kernel 5: residual + LayerNorm --------------------------
__global__ void ln_kernel(const float* __restrict__ hs,
                          const float* __restrict__ gamma,
                          const float* __restrict__ beta,
                          float* __restrict__ out) {
    const int t = blockIdx.x;
    const int tid = threadIdx.x;
    const float* a = hs + (size_t)t * H;
    const float* c = g_comb + (size_t)t * H;

    float v[4];
    float s = 0.0f;
#pragma unroll
    for (int i = 0; i < 4; i++) {
        int h = tid + i * 256;
        v[i] = a[h] + c[h];
        s += v[i];
    }
    __shared__ float red[256];
    red[tid] = s;
    __syncthreads();
    for (int o = 128; o > 0; o >>= 1) {
        if (tid < o) red[tid] += red[tid + o];
        __syncthreads();
    }
    float mu = red[0] * (1.0f / H);
    float s2 = 0.0f;
#pragma unroll
    for (int i = 0; i < 4; i++) {
        float d = v[i] - mu;
        s2 += d * d;
    }
    __syncthreads();
    red[tid] = s2;
    __syncthreads();
    for (int o = 128; o > 0; o >>= 1) {
        if (tid < o) red[tid] += red[tid + o];
        __syncthreads();
    }
    float var = red[0] * (1.0f / H);
    float rs = rsqrtf(var + 1e-5f);
#pragma unroll
    for (int i = 0; i < 4; i++) {
        int h = tid + i * 256;
        out[(size_t)t * H + h] = (v[i] - mu) * rs * gamma[h] + beta[h];
    }
}

// ---------------- launch ---------------------------------------------------
extern "C" void kernel_launch(void* const* d_in, const int* in_sizes, int n_in,
                              void* d_out, int out_size) {
    const float* hs    = (const float*)d_in[0];   // [N, H]
    const float* Wr    = (const float*)d_in[1];   // [H, E]
    const float* br    = (const float*)d_in[2];   // [E]
    const float* W1    = (const float*)d_in[3];   // [E, H, F]
    const float* b1    = (const float*)d_in[4];   // [E, F]
    const float* W2    = (const float*)d_in[5];   // [E, F, H]
    const float* b2    = (const float*)d_in[6];   // [E, H]
    const float* gamma = (const float*)d_in[7];   // [H]
    const float* beta  = (const float*)d_in[8];   // [H]
    float* out = (float*)d_out;

    zero_kernel<<<2048, 256>>>();
    router_kernel<<<(NTOK * 32) / 256, 256>>>(hs, Wr, br);
    rank_kernel<<<dim3(E, 8), 256>>>();
    gemm1_kernel<<<dim3(F / 128, CAP / 128, E), 256>>>(hs, W1, b1);
    gemm2_kernel<<<dim3(H / 128, CAP / 128, E), 256>>>(W2, b2);
    ln_kernel<<<NTOK, 256>>>(hs, gamma, beta, out);
}

// round 8
// speedup vs baseline: 1.0573x; 1.0573x over previous
#include <cuda_runtime.h>
#include <cuda_bf16.h>
#include <cstdint>
#include <math.h>

// ---------------- problem constants ----------------
#define NTOK 8192
#define H    1024
#define F    4096
#define E    8
#define TOPK 2
#define CAP  1280
#define MAXL NTOK

// ---------------- device scratch (bss) ----------------
__device__ float              g_comb[(size_t)NTOK * H];     // combine buffer
__device__ float              g_h1[(size_t)E * CAP * F];    // fp32 intermediate
__device__ unsigned long long g_key[E * MAXL];
__device__ int                g_aid[E * MAXL];
__device__ int                g_cnt[E];
__device__ int                g_kept[E];
__device__ int                g_tok[E * CAP];
__device__ float              g_gate[E * CAP];

// ---------------- helpers ----------------
typedef unsigned long long u64;

__device__ __forceinline__ uint32_t smem_u32(const void* p) {
    uint32_t a;
    asm("{ .reg .u64 t; cvta.to.shared.u64 t, %1; cvt.u32.u64 %0, t; }" : "=r"(a) : "l"(p));
    return a;
}
__device__ __forceinline__ void cp16(uint32_t dst, const void* src) {
    asm volatile("cp.async.cg.shared.global [%0], [%1], 16;" :: "r"(dst), "l"(src) : "memory");
}
#define CP_COMMIT() asm volatile("cp.async.commit_group;" ::: "memory")
#define CP_WAIT1()  asm volatile("cp.async.wait_group 1;" ::: "memory")
#define CP_WAIT0()  asm volatile("cp.async.wait_group 0;" ::: "memory")

__device__ __forceinline__ u64 pack2(float x, float y) {
    u64 r;
    asm("mov.b64 %0, {%1, %2};" : "=l"(r) : "f"(x), "f"(y));
    return r;
}
__device__ __forceinline__ void fma2(u64& c, u64 a, u64 b) {
    asm("fma.rn.f32x2 %0, %1, %2, %0;" : "+l"(c) : "l"(a), "l"(b));
}
__device__ __forceinline__ void unpack2(u64 v, float& x, float& y) {
    asm("mov.b64 {%0, %1}, %2;" : "=f"(x), "=f"(y) : "l"(v));
}
__device__ __forceinline__ float gelu_erf(float v) {
    return 0.5f * v * (1.0f + erff(v * 0.70710678118654752440f));
}

// ---------------- zero combine + counters ----------------
__global__ void zero_kernel() {
    size_t idx = (size_t)blockIdx.x * blockDim.x + threadIdx.x;
    size_t total = (size_t)NTOK * H;
    for (size_t i = idx; i < total; i += (size_t)gridDim.x * blockDim.x)
        g_comb[i] = 0.0f;
    if (idx < E) g_cnt[idx] = 0;
}

// ---------------- router (exact fp32) ----------------
__global__ void router_kernel(const float* __restrict__ x,
                              const float* __restrict__ Wr,
                              const float* __restrict__ br) {
    int warp = (blockIdx.x * blockDim.x + threadIdx.x) >> 5;
    int lane = threadIdx.x & 31;
    if (warp >= NTOK) return;
    const float* xr = x + (size_t)warp * H;
    float acc[E];
#pragma unroll
    for (int e = 0; e < E; e++) acc[e] = 0.0f;
    for (int k = lane; k < H; k += 32) {
        float xv = xr[k];
        const float* w = Wr + (size_t)k * E;
#pragma unroll
        for (int e = 0; e < E; e++) acc[e] += xv * w[e];
    }
#pragma unroll
    for (int e = 0; e < E; e++) {
#pragma unroll
        for (int off = 16; off > 0; off >>= 1)
            acc[e] += __shfl_xor_sync(0xffffffffu, acc[e], off);
    }
    if (lane == 0) {
        float lg[E];
#pragma unroll
        for (int e = 0; e < E; e++) lg[e] = acc[e] + br[e];
        float b1v = -1e38f; int b1i = 0;
#pragma unroll
        for (int e = 0; e < E; e++)
            if (lg[e] > b1v) { b1v = lg[e]; b1i = e; }
        float b2v = -1e38f; int b2i = 0;
#pragma unroll
        for (int e = 0; e < E; e++)
            if (e != b1i && lg[e] > b2v) { b2v = lg[e]; b2i = e; }
        float ed = expf(b2v - b1v);
        float inv = 1.0f / (1.0f + ed);
        float w1 = inv, w2 = ed * inv;
        int a0 = warp * TOPK, a1 = a0 + 1;
        unsigned long long k0 =
            ((unsigned long long)__float_as_uint(w1) << 32) | (0xFFFFFFFFu - (unsigned)a0);
        unsigned long long k1 =
            ((unsigned long long)__float_as_uint(w2) << 32) | (0xFFFFFFFFu - (unsigned)a1);
        int p0 = atomicAdd(&g_cnt[b1i], 1);
        g_key[b1i * MAXL + p0] = k0;
        g_aid[b1i * MAXL + p0] = a0;
        int p1 = atomicAdd(&g_cnt[b2i], 1);
        g_key[b2i * MAXL + p1] = k1;
        g_aid[b2i * MAXL + p1] = a1;
    }
}

// ---------------- rank & compact (exact jax top_k semantics) ----------------
__global__ void rank_kernel() {
    int e = blockIdx.x;
    int Le = g_cnt[e];
    if (blockIdx.y == 0 && threadIdx.x == 0)
        g_kept[e] = (Le < CAP) ? Le : CAP;
    const unsigned long long* keys = g_key + e * MAXL;
    for (int i = blockIdx.y * blockDim.x + threadIdx.x; i < Le;
         i += gridDim.y * blockDim.x) {
        unsigned long long ki = keys[i];
        int rank = 0;
        for (int j = 0; j < Le; j++)
            rank += (keys[j] > ki) ? 1 : 0;
        if (rank < CAP) {
            int a = g_aid[e * MAXL + i];
            g_tok[e * CAP + rank]  = a >> 1;
            g_gate[e * CAP + rank] = __uint_as_float((unsigned)(ki >> 32));
        }
    }
}

// ---------------- f32x2 SGEMM geometry ----------------
// CTA tile 128x128, 256 threads, 8x8 microtile (as 8x4 f32x2 pairs).
// K-tile 16, double-buffered cp.async.
// As [128][KP=20] m-major (float4 over k); Bs [16][128] k-rows (float4 over n).
#define KP 20

// Shared inner-product core: accp[8][4] += A-frag x B-frag over 16 k's.
#define GEMM_CORE(Ab, Bb)                                                       \
    do {                                                                        \
        _Pragma("unroll")                                                       \
        for (int k4 = 0; k4 < 4; k4++) {                                        \
            float4 a4[8];                                                       \
            _Pragma("unroll")                                                   \
            for (int i = 0; i < 8; i++)                                         \
                a4[i] = *(const float4*)&(Ab)[(ty * 8 + i) * KP + k4 * 4];      \
            _Pragma("unroll")                                                   \
            for (int kk = 0; kk < 4; kk++) {                                    \
                int kidx = k4 * 4 + kk;                                         \
                float4 bv0 = *(const float4*)&(Bb)[kidx * 128 + tx * 8];        \
                float4 bv1 = *(const float4*)&(Bb)[kidx * 128 + tx * 8 + 4];    \
                u64 bp0 = pack2(bv0.x, bv0.y), bp1 = pack2(bv0.z, bv0.w);       \
                u64 bp2 = pack2(bv1.x, bv1.y), bp3 = pack2(bv1.z, bv1.w);       \
                _Pragma("unroll")                                               \
                for (int i = 0; i < 8; i++) {                                   \
                    float av = (kk == 0) ? a4[i].x : (kk == 1) ? a4[i].y        \
                             : (kk == 2) ? a4[i].z : a4[i].w;                   \
                    u64 ap = pack2(av, av);                                     \
                    fma2(accp[i][0], ap, bp0);                                  \
                    fma2(accp[i][1], ap, bp1);                                  \
                    fma2(accp[i][2], ap, bp2);                                  \
                    fma2(accp[i][3], ap, bp3);                                  \
                }                                                               \
            }                                                                   \
        }                                                                       \
    } while (0)

// ---------------- GEMM1: h1 = gelu(gather(x) @ W1 + b1) ----------------
__global__ __launch_bounds__(256)
void gemm1_k(const float* __restrict__ x,
             const float* __restrict__ W1,
             const float* __restrict__ b1) {
    const int e = blockIdx.z;
    const int kept = g_kept[e];
    const int rowBase = blockIdx.y * 128;
    if (rowBase >= kept) return;
    const int colBase = blockIdx.x * 128;

    __shared__ float As[2][128 * KP];
    __shared__ float Bs[2][16 * 128];
    __shared__ int   tokS[128];
    __shared__ float biasS[128];

    const int tid = threadIdx.x;
    if (tid < 128) {
        int gr = rowBase + tid;
        tokS[tid]  = (gr < kept) ? g_tok[e * CAP + gr] : 0;
        biasS[tid] = b1[(size_t)e * F + colBase + tid];
    }
    __syncthreads();

    const int ty = tid >> 4, tx = tid & 15;
    const int lm = tid >> 1;                 // loader row (A)
    const int lk = (tid & 1) * 2;            // loader k4-pair base
    const int myTok = tokS[lm];
    const float* Bglob = W1 + (size_t)e * H * F + colBase;
    uint32_t aB[2] = { smem_u32(&As[0][0]), smem_u32(&As[1][0]) };
    uint32_t bB[2] = { smem_u32(&Bs[0][0]), smem_u32(&Bs[1][0]) };

    u64 accp[8][4] = {};

    auto loadStage = [&](int c, int st) {
        int k0 = c * 16;
        // A: 128 rows x 16 k = 512 float4; thread -> row lm, k4 = lk, lk+1
        cp16(aB[st] + (uint32_t)(lm * KP + lk * 4) * 4,
             x + (size_t)myTok * H + k0 + lk * 4);
        cp16(aB[st] + (uint32_t)(lm * KP + (lk + 1) * 4) * 4,
             x + (size_t)myTok * H + k0 + (lk + 1) * 4);
        // B: 16 k-rows x 128 n = 512 float4; chunks c2 = tid*2+{0,1}
#pragma unroll
        for (int i = 0; i < 2; i++) {
            int c2 = tid * 2 + i;
            int kr = c2 >> 5, n4 = c2 & 31;
            cp16(bB[st] + (uint32_t)(kr * 128 + n4 * 4) * 4,
                 Bglob + (size_t)(k0 + kr) * F + n4 * 4);
        }
        CP_COMMIT();
    };

    const int NC = H / 16;
    loadStage(0, 0);
    for (int c = 0; c < NC; c++) {
        int st = c & 1;
        if (c + 1 < NC) { loadStage(c + 1, st ^ 1); CP_WAIT1(); }
        else CP_WAIT0();
        __syncthreads();
        const float* Ab = As[st];
        const float* Bb = Bs[st];
        GEMM_CORE(Ab, Bb);
        __syncthreads();
    }

    // epilogue: +bias, erf-GELU, store h1
#pragma unroll
    for (int i = 0; i < 8; i++) {
        int gr = rowBase + ty * 8 + i;
        if (gr >= kept) continue;
        float* hrow = g_h1 + ((size_t)e * CAP + gr) * F + colBase + tx * 8;
        float4 o0, o1;
        float v0, v1;
        unpack2(accp[i][0], v0, v1);
        o0.x = gelu_erf(v0 + biasS[tx * 8 + 0]);
        o0.y = gelu_erf(v1 + biasS[tx * 8 + 1]);
        unpack2(accp[i][1], v0, v1);
        o0.z = gelu_erf(v0 + biasS[tx * 8 + 2]);
        o0.w = gelu_erf(v1 + biasS[tx * 8 + 3]);
        unpack2(accp[i][2], v0, v1);
        o1.x = gelu_erf(v0 + biasS[tx * 8 + 4]);
        o1.y = gelu_erf(v1 + biasS[tx * 8 + 5]);
        unpack2(accp[i][3], v0, v1);
        o1.z = gelu_erf(v0 + biasS[tx * 8 + 6]);
        o1.w = gelu_erf(v1 + biasS[tx * 8 + 7]);
        *(float4*)(hrow)     = o0;
        *(float4*)(hrow + 4) = o1;
    }
}

// ---------------- GEMM2: comb[tok] += gate * (h1 @ W2 + b2) ----------------
__global__ __launch_bounds__(256)
void gemm2_k(const float* __restrict__ W2,
             const float* __restrict__ b2) {
    const int e = blockIdx.z;
    const int kept = g_kept[e];
    const int rowBase = blockIdx.y * 128;
    if (rowBase >= kept) return;
    const int colBase = blockIdx.x * 128;

    __shared__ float As[2][128 * KP];
    __shared__ float Bs[2][16 * 128];
    __shared__ int   tokS[128];
    __shared__ float gateS[128];
    __shared__ float biasS[128];

    const int tid = threadIdx.x;
    if (tid < 128) {
        int gr = rowBase + tid;
        tokS[tid]  = (gr < kept) ? g_tok[e * CAP + gr] : 0;
        gateS[tid] = (gr < kept) ? g_gate[e * CAP + gr] : 0.0f;
        biasS[tid] = b2[(size_t)e * H + colBase + tid];
    }
    __syncthreads();

    const int ty = tid >> 4, tx = tid & 15;
    const int lm = tid >> 1;
    const int lk = (tid & 1) * 2;
    const float* Arow  = g_h1 + ((size_t)e * CAP + rowBase + lm) * F;
    const float* Bglob = W2 + (size_t)e * F * H + colBase;
    uint32_t aB[2] = { smem_u32(&As[0][0]), smem_u32(&As[1][0]) };
    uint32_t bB[2] = { smem_u32(&Bs[0][0]), smem_u32(&Bs[1][0]) };

    u64 accp[8][4] = {};

    auto loadStage = [&](int c, int st) {
        int k0 = c * 16;
        cp16(aB[st] + (uint32_t)(lm * KP + lk * 4) * 4, Arow + k0 + lk * 4);
        cp16(aB[st] + (uint32_t)(lm * KP + (lk + 1) * 4) * 4, Arow + k0 + (lk + 1) * 4);
#pragma unroll
        for (int i = 0; i < 2; i++) {
            int c2 = tid * 2 + i;
            int kr = c2 >> 5, n4 = c2 & 31;
            cp16(bB[st] + (uint32_t)(kr * 128 + n4 * 4) * 4,
                 Bglob + (size_t)(k0 + kr) * H + n4 * 4);
        }
        CP_COMMIT();
    };

    const int NC = F / 16;
    loadStage(0, 0);
    for (int c = 0; c < NC; c++) {
        int st = c & 1;
        if (c + 1 < NC) { loadStage(c + 1, st ^ 1); CP_WAIT1(); }
        else CP_WAIT0();
        __syncthreads();
        const float* Ab = As[st];
        const float* Bb = Bs[st];
        GEMM_CORE(Ab, Bb);
        __syncthreads();
    }

    // epilogue: +bias, gate-scale, atomic scatter-add into combine buffer
#pragma unroll
    for (int i = 0; i < 8; i++) {
        int lr = ty * 8 + i;
        int gr = rowBase + lr;
        if (gr >= kept) continue;
        float gt = gateS[lr];
        float* dst = &g_comb[(size_t)tokS[lr] * H + colBase + tx * 8];
        float v0, v1;
        unpack2(accp[i][0], v0, v1);
        atomicAdd(dst + 0, (v0 + biasS[tx * 8 + 0]) * gt);
        atomicAdd(dst + 1, (v1 + biasS[tx * 8 + 1]) * gt);
        unpack2(accp[i][1], v0, v1);
        atomicAdd(dst + 2, (v0 + biasS[tx * 8 + 2]) * gt);
        atomicAdd(dst + 3, (v1 + biasS[tx * 8 + 3]) * gt);
        unpack2(accp[i][2], v0, v1);
        atomicAdd(dst + 4, (v0 + biasS[tx * 8 + 4]) * gt);
        atomicAdd(dst + 5, (v1 + biasS[tx * 8 + 5]) * gt);
        unpack2(accp[i][3], v0, v1);
        atomicAdd(dst + 6, (v0 + biasS[tx * 8 + 6]) * gt);
        atomicAdd(dst + 7, (v1 + biasS[tx * 8 + 7]) * gt);
    }
}

// ---------------- residual + LayerNorm ----------------
__global__ void ln_kernel(const float* __restrict__ hs,
                          const float* __restrict__ gamma,
                          const float* __restrict__ beta,
                          float* __restrict__ out) {
    const int t = blockIdx.x;
    const int tid = threadIdx.x;
    const float* a = hs + (size_t)t * H;
    const float* c = g_comb + (size_t)t * H;
    float v[4];
    float s = 0.0f;
#pragma unroll
    for (int i = 0; i < 4; i++) {
        int h = tid + i * 256;
        v[i] = a[h] + c[h];
        s += v[i];
    }
    __shared__ float red[256];
    red[tid] = s;
    __syncthreads();
    for (int o = 128; o > 0; o >>= 1) {
        if (tid < o) red[tid] += red[tid + o];
        __syncthreads();
    }
    float mu = red[0] * (1.0f / H);
    float s2 = 0.0f;
#pragma unroll
    for (int i = 0; i < 4; i++) {
        float d = v[i] - mu;
        s2 += d * d;
    }
    __syncthreads();
    red[tid] = s2;
    __syncthreads();
    for (int o = 128; o > 0; o >>= 1) {
        if (tid < o) red[tid] += red[tid + o];
        __syncthreads();
    }
    float var = red[0] * (1.0f / H);
    float rs = rsqrtf(var + 1e-5f);
#pragma unroll
    for (int i = 0; i < 4; i++) {
        int h = tid + i * 256;
        out[(size_t)t * H + h] = (v[i] - mu) * rs * gamma[h] + beta[h];
    }
}

// ---------------- launch ----------------
extern "C" void kernel_launch(void* const* d_in, const int* in_sizes, int n_in,
                              void* d_out, int out_size) {
    const float* hs    = (const float*)d_in[0];
    const float* Wr    = (const float*)d_in[1];
    const float* br    = (const float*)d_in[2];
    const float* W1    = (const float*)d_in[3];
    const float* b1    = (const float*)d_in[4];
    const float* W2    = (const float*)d_in[5];
    const float* b2    = (const float*)d_in[6];
    const float* gamma = (const float*)d_in[7];
    const float* beta  = (const float*)d_in[8];
    float* out = (float*)d_out;

    zero_kernel<<<2048, 256>>>();
    router_kernel<<<(NTOK * 32) / 256, 256>>>(hs, Wr, br);
    rank_kernel<<<dim3(E, 8), 256>>>();
    gemm1_k<<<dim3(F / 128, CAP / 128, E), 256>>>(hs, W1, b1);
    gemm2_k<<<dim3(H / 128, CAP / 128, E), 256>>>(W2, b2);
    ln_kernel<<<NTOK, 256>>>(hs, gamma, beta, out);
}